// round 11
// baseline (speedup 1.0000x reference)
#include <cuda_runtime.h>
#include <math.h>

#define MU_ELEMS (32*100*64)      // 204800
#define SG_ELEMS (32*100*100*64)  // 20480000

// 640 blocks = 32 b x 20 p-strips (5 p each), 256 threads (8 warps):
//  w0-3: Gram strip G[5p][100q], kk-split 4-way, 4 q/lane in regs, p broadcast
//        (partials: w0/w1 store to sGp[0/1], then w2/w3 add into them)
//  w4-5: conv (mu_out), kk-split 2-way, k=lane/lane+32, 5 ox
//  w6-7: diag_vals, same layout over Sigma-diag window
__global__ __launch_bounds__(256) void fused_kernel(
    const float* __restrict__ mu_in, const float* __restrict__ Sigma_in,
    const float* __restrict__ w_mu, const float* __restrict__ w_sigma,
    float* __restrict__ mu_out, float* __restrict__ sigma_out)
{
    __shared__ __align__(16) float smu[196 * 36];  // 28224 B: mu_in[b], n-major, pad 36
    __shared__ __align__(16) float sds[2240];      //  8960 B: Sigma diag window 5x14x32
    __shared__ __align__(16) float sGp[2][500];    //  4000 B: Gram partials [buf][pl*100+q]
    __shared__ __align__(16) float pcv[2][320];    //  2560 B: conv partials [kg][pl*64+k]
    __shared__ __align__(16) float pdi[2][320];    //  2560 B: diag partials
    __shared__ __align__(16) float ssp[64];        //   256 B  (total 46560 < 49152)

    const int bid = blockIdx.x;
    const int b   = bid / 20;
    const int pt  = bid % 20;
    const int oy  = pt >> 1;
    const int oxb = (pt & 1) * 5;
    const int tid = threadIdx.x;
    const int w    = tid >> 5;
    const int lane = tid & 31;

    for (int i = tid; i < 6272; i += 256) {
        int n = i >> 5, c = i & 31;
        smu[n * 36 + c] = mu_in[(size_t)(b * 196 + n) * 32 + c];
    }
    for (int i = tid; i < 2240; i += 256) {
        int r = i / 448, rem = i - r * 448;
        int x = rem >> 5, c = rem & 31;
        int n = (oy + r) * 14 + x;
        sds[i] = Sigma_in[(((size_t)b * 196 + n) * 196 + n) * 32 + c];
    }
    if (tid < 64) ssp[tid] = log1pf(expf(w_sigma[tid]));
    __syncthreads();

    float gacc[4][5];       // Gram accumulators (kept across barrier for w2/w3)
    int q[4];

    if (w < 4) {
        // ---------------- GRAM ----------------
        const int kk0 = (w == 0) ? 0 : (w == 1) ? 7 : (w == 2) ? 13 : 19;
        const int kk1 = (w == 0) ? 7 : (w == 1) ? 13 : (w == 2) ? 19 : 25;
        int nq[4];
        #pragma unroll
        for (int j = 0; j < 4; j++) {
            q[j] = lane + j * 32;
            int qc = (q[j] < 100) ? q[j] : 0;
            nq[j] = (qc / 10) * 14 + qc % 10;
        }
        #pragma unroll
        for (int j = 0; j < 4; j++)
            #pragma unroll
            for (int pl = 0; pl < 5; pl++) gacc[j][pl] = 0.f;

        const int prow0 = oy * 14 + oxb;
        #pragma unroll 1
        for (int kk = kk0; kk < kk1; kk++) {
            const int off = (kk / 5) * 14 + (kk % 5);
            const float* b0 = smu + (nq[0] + off) * 36;
            const float* b1 = smu + (nq[1] + off) * 36;
            const float* b2 = smu + (nq[2] + off) * 36;
            const float* b3 = smu + (nq[3] + off) * 36;
            const float* ar = smu + (prow0 + off) * 36;
            #pragma unroll
            for (int c4 = 0; c4 < 8; c4++) {
                float4 qv0 = *(const float4*)(b0 + c4 * 4);
                float4 qv1 = *(const float4*)(b1 + c4 * 4);
                float4 qv2 = *(const float4*)(b2 + c4 * 4);
                float4 qv3 = *(const float4*)(b3 + c4 * 4);
                #pragma unroll
                for (int pl = 0; pl < 5; pl++) {
                    float4 av = *(const float4*)(ar + pl * 36 + c4 * 4); // broadcast
                    gacc[0][pl] = fmaf(av.x, qv0.x, gacc[0][pl]);
                    gacc[0][pl] = fmaf(av.y, qv0.y, gacc[0][pl]);
                    gacc[0][pl] = fmaf(av.z, qv0.z, gacc[0][pl]);
                    gacc[0][pl] = fmaf(av.w, qv0.w, gacc[0][pl]);
                    gacc[1][pl] = fmaf(av.x, qv1.x, gacc[1][pl]);
                    gacc[1][pl] = fmaf(av.y, qv1.y, gacc[1][pl]);
                    gacc[1][pl] = fmaf(av.z, qv1.z, gacc[1][pl]);
                    gacc[1][pl] = fmaf(av.w, qv1.w, gacc[1][pl]);
                    gacc[2][pl] = fmaf(av.x, qv2.x, gacc[2][pl]);
                    gacc[2][pl] = fmaf(av.y, qv2.y, gacc[2][pl]);
                    gacc[2][pl] = fmaf(av.z, qv2.z, gacc[2][pl]);
                    gacc[2][pl] = fmaf(av.w, qv2.w, gacc[2][pl]);
                    gacc[3][pl] = fmaf(av.x, qv3.x, gacc[3][pl]);
                    gacc[3][pl] = fmaf(av.y, qv3.y, gacc[3][pl]);
                    gacc[3][pl] = fmaf(av.z, qv3.z, gacc[3][pl]);
                    gacc[3][pl] = fmaf(av.w, qv3.w, gacc[3][pl]);
                }
            }
        }
        if (w < 2) {        // w0/w1: store partials into their buffer
            #pragma unroll
            for (int j = 0; j < 4; j++) {
                if (q[j] < 100) {
                    #pragma unroll
                    for (int pl = 0; pl < 5; pl++)
                        sGp[w][pl * 100 + q[j]] = gacc[j][pl];
                }
            }
        }
    } else if (w < 6) {
        // ---------------- CONV ----------------
        const int kg  = w - 4;
        const int kk0 = kg ? 13 : 0;
        const int kk1 = kg ? 25 : 13;
        const float* wk = w_mu + lane;
        float acc[10];
        #pragma unroll
        for (int j = 0; j < 10; j++) acc[j] = 0.f;

        #pragma unroll 1
        for (int kk = kk0; kk < kk1; kk++) {
            const int off = (kk / 5) * 14 + (kk % 5);
            const float* mrow = smu + (oy * 14 + oxb + off) * 36;
            #pragma unroll
            for (int c4 = 0; c4 < 8; c4++) {
                const int m = kk * 32 + c4 * 4;
                float wa0 = wk[(m + 0) * 64], wb0 = wk[(m + 0) * 64 + 32];
                float wa1 = wk[(m + 1) * 64], wb1 = wk[(m + 1) * 64 + 32];
                float wa2 = wk[(m + 2) * 64], wb2 = wk[(m + 2) * 64 + 32];
                float wa3 = wk[(m + 3) * 64], wb3 = wk[(m + 3) * 64 + 32];
                #pragma unroll
                for (int j = 0; j < 5; j++) {
                    float4 mv = *(const float4*)(mrow + j * 36 + c4 * 4);
                    acc[j]     = fmaf(mv.x, wa0, acc[j]);
                    acc[j]     = fmaf(mv.y, wa1, acc[j]);
                    acc[j]     = fmaf(mv.z, wa2, acc[j]);
                    acc[j]     = fmaf(mv.w, wa3, acc[j]);
                    acc[5 + j] = fmaf(mv.x, wb0, acc[5 + j]);
                    acc[5 + j] = fmaf(mv.y, wb1, acc[5 + j]);
                    acc[5 + j] = fmaf(mv.z, wb2, acc[5 + j]);
                    acc[5 + j] = fmaf(mv.w, wb3, acc[5 + j]);
                }
            }
        }
        #pragma unroll
        for (int j = 0; j < 5; j++) {
            pcv[kg][j * 64 + lane]      = acc[j];
            pcv[kg][j * 64 + 32 + lane] = acc[5 + j];
        }
    } else {
        // ---------------- DIAG ----------------
        const int kg  = w - 6;
        const int kk0 = kg ? 13 : 0;
        const int kk1 = kg ? 25 : 13;
        const float* wk = w_mu + lane;
        const float spa = ssp[lane], spb = ssp[lane + 32];
        float acc[10];
        #pragma unroll
        for (int j = 0; j < 10; j++) acc[j] = 0.f;

        #pragma unroll 1
        for (int kk = kk0; kk < kk1; kk++) {
            const float* drow = sds + ((kk / 5) * 14 + (kk % 5) + oxb) * 32;
            #pragma unroll
            for (int c4 = 0; c4 < 8; c4++) {
                const int m = kk * 32 + c4 * 4;
                float wa0 = wk[(m + 0) * 64], wb0 = wk[(m + 0) * 64 + 32];
                float wa1 = wk[(m + 1) * 64], wb1 = wk[(m + 1) * 64 + 32];
                float wa2 = wk[(m + 2) * 64], wb2 = wk[(m + 2) * 64 + 32];
                float wa3 = wk[(m + 3) * 64], wb3 = wk[(m + 3) * 64 + 32];
                float ea0 = fmaf(wa0, wa0, spa), eb0 = fmaf(wb0, wb0, spb);
                float ea1 = fmaf(wa1, wa1, spa), eb1 = fmaf(wb1, wb1, spb);
                float ea2 = fmaf(wa2, wa2, spa), eb2 = fmaf(wb2, wb2, spb);
                float ea3 = fmaf(wa3, wa3, spa), eb3 = fmaf(wb3, wb3, spb);
                #pragma unroll
                for (int j = 0; j < 5; j++) {
                    float4 dv = *(const float4*)(drow + j * 32 + c4 * 4);
                    acc[j]     = fmaf(dv.x, ea0, acc[j]);
                    acc[j]     = fmaf(dv.y, ea1, acc[j]);
                    acc[j]     = fmaf(dv.z, ea2, acc[j]);
                    acc[j]     = fmaf(dv.w, ea3, acc[j]);
                    acc[5 + j] = fmaf(dv.x, eb0, acc[5 + j]);
                    acc[5 + j] = fmaf(dv.y, eb1, acc[5 + j]);
                    acc[5 + j] = fmaf(dv.z, eb2, acc[5 + j]);
                    acc[5 + j] = fmaf(dv.w, eb3, acc[5 + j]);
                }
            }
        }
        #pragma unroll
        for (int j = 0; j < 5; j++) {
            pdi[kg][j * 64 + lane]      = acc[j];
            pdi[kg][j * 64 + 32 + lane] = acc[5 + j];
        }
    }
    __syncthreads();

    // w2/w3 accumulate their Gram partials into sGp[0]/sGp[1] (disjoint lanes/q)
    if (w == 2 || w == 3) {
        const int buf = w - 2;
        #pragma unroll
        for (int j = 0; j < 4; j++) {
            if (q[j] < 100) {
                #pragma unroll
                for (int pl = 0; pl < 5; pl++)
                    sGp[buf][pl * 100 + q[j]] += gacc[j][pl];
            }
        }
    }
    __syncthreads();

    // merge buffers; write mu_out
    for (int i = tid; i < 500; i += 256)
        sGp[0][i] += sGp[1][i];
    if (mu_out != nullptr) {
        for (int i = tid; i < 320; i += 256) {
            int pl = i >> 6, k = i & 63;
            mu_out[(b * 100 + pt * 5 + pl) * 64 + k] = pcv[0][i] + pcv[1][i];
        }
    }
    __syncthreads();

    if (sigma_out == nullptr) return;

    // patch diagonal entries (q == p): add diag_vals, then abs where q==k
    for (int i = tid; i < 320; i += 256) {
        int pl = i >> 6, k = i & 63;
        int pg = pt * 5 + pl;
        float val = ssp[k] * sGp[0][pl * 100 + pg] + pdi[0][i] + pdi[1][i];
        if (pg == k) val = fabsf(val);
        sigma_out[(((size_t)(b * 100 + pg)) * 100 + pg) * 64 + k] = val;
    }

    // writer: all (p in strip, q != p, k): sp[k]*G, abs at q==k
    const float4* sp4 = (const float4*)ssp;
    float4* out4 = (float4*)sigma_out;
    for (int idx = tid; idx < 8000; idx += 256) {
        const int kq = idx & 15;
        const int t  = idx >> 4;
        const int ql = t % 100, pl = t / 100;
        const int pg = pt * 5 + pl;
        if (ql == pg) continue;                 // diagonal handled by patch
        const float g = sGp[0][pl * 100 + ql];
        const float4 s4 = sp4[kq];
        float4 v;
        v.x = s4.x * g; v.y = s4.y * g; v.z = s4.z * g; v.w = s4.w * g;
        const int k0 = kq * 4;
        if      (ql == k0    ) v.x = fabsf(v.x);
        else if (ql == k0 + 1) v.y = fabsf(v.y);
        else if (ql == k0 + 2) v.z = fabsf(v.z);
        else if (ql == k0 + 3) v.w = fabsf(v.w);
        out4[((size_t)(b * 100 + pg) * 100 + ql) * 16 + kq] = v;
    }
}

extern "C" void kernel_launch(void* const* d_in, const int* in_sizes, int n_in,
                              void* d_out, int out_size)
{
    const float* mu_in    = (const float*)d_in[0];
    const float* Sigma_in = (const float*)d_in[1];
    const float* w_mu     = (const float*)d_in[2];
    const float* w_sigma  = (const float*)d_in[3];
    for (int i = 0; i < n_in && i < 8; i++) {
        switch (in_sizes[i]) {
            case 32*14*14*32:  mu_in    = (const float*)d_in[i]; break;
            case 39337984:     Sigma_in = (const float*)d_in[i]; break;
            case 5*5*32*64:    w_mu     = (const float*)d_in[i]; break;
            case 64:           w_sigma  = (const float*)d_in[i]; break;
            default: break;
        }
    }

    float* out = (float*)d_out;
    float* mu_ptr  = nullptr;
    float* sig_ptr = nullptr;
    if (out_size == MU_ELEMS + SG_ELEMS) { mu_ptr = out; sig_ptr = out + MU_ELEMS; }
    else if (out_size == SG_ELEMS)       { sig_ptr = out; }
    else if (out_size == MU_ELEMS)       { mu_ptr = out; }
    else                                 { mu_ptr = out; sig_ptr = out + MU_ELEMS; }

    fused_kernel<<<640, 256>>>(mu_in, Sigma_in, w_mu, w_sigma, mu_ptr, sig_ptr);
}